// round 6
// baseline (speedup 1.0000x reference)
#include <cuda_runtime.h>

// LSTM: B=2048, T=512, I=1, H=64, gates=256 (i,f,g,o), O=1. fp32 throughout.
// Grid: 512 CTAs x 128 threads. Each CTA owns RPB=4 batch rows for the whole
// T=512 recurrence (no cross-CTA traffic). Thread t owns gate rows t and
// t+128 of W_hh in registers (packed as f32x2 pairs over k) and computes
// those two gate pre-activations for all 4 rows each step via fma.rn.f32x2.
// h lives in SMEM (broadcast reads); c lives in registers of the phase-2
// owner thread. Two __syncthreads per step.

#define BATCH 2048
#define TSTEPS 512
#define HID 64
#define G4 256
#define RPB 4
#define NTHR 128

typedef unsigned long long u64;

__device__ __forceinline__ void fma2(u64 &acc, u64 a, u64 b) {
    asm("fma.rn.f32x2 %0, %1, %2, %0;" : "+l"(acc) : "l"(a), "l"(b));
}

__device__ __forceinline__ float2 unpack2(u64 v) {
    float2 r;
    asm("mov.b64 {%0, %1}, %2;" : "=f"(r.x), "=f"(r.y) : "l"(v));
    return r;
}

// sigmoid(x) = 1 / (1 + 2^(-x*log2e)).  ex2.approx/rcp.approx err ~2^-22.
// x -> -inf: ex2 -> +inf, rcp(inf)=0  (correct). x -> +inf: ex2 -> 0, rcp(1)=1.
__device__ __forceinline__ float fast_sigmoid(float x) {
    float e, r;
    asm("ex2.approx.f32 %0, %1;" : "=f"(e) : "f"(x * -1.4426950408889634f));
    asm("rcp.approx.f32 %0, %1;" : "=f"(r) : "f"(1.0f + e));
    return r;
}

// tanh(x) = 1 - 2 / (1 + 2^(x*2*log2e)).  Saturates correctly at +-inf.
__device__ __forceinline__ float fast_tanh(float x) {
    float e, r;
    asm("ex2.approx.f32 %0, %1;" : "=f"(e) : "f"(x * 2.8853900817779268f));
    asm("rcp.approx.f32 %0, %1;" : "=f"(r) : "f"(1.0f + e));
    return fmaf(-2.0f, r, 1.0f);
}

__global__ __launch_bounds__(NTHR)
void lstm_fused_kernel(const float* __restrict__ x,      // [B, T, 1]
                       const float* __restrict__ w_ih,   // [256, 1]
                       const float* __restrict__ w_hh,   // [256, 64]
                       const float* __restrict__ b_ih,   // [256]
                       const float* __restrict__ b_hh,   // [256]
                       const float* __restrict__ w_lin,  // [1, 64]
                       const float* __restrict__ b_lin,  // [1]
                       float* __restrict__ out)          // [B, 1]
{
    __shared__ float sh_x[RPB * TSTEPS];   // 8 KB: x for the 4 rows
    __shared__ float sh_h[RPB][HID];       // 1 KB: current h (rows 16B-aligned)
    __shared__ float sh_g[RPB][G4];        // 4 KB: activated gates this step

    const int t  = threadIdx.x;
    const int b0 = blockIdx.x * RPB;
    const int j0 = t;          // gate row A: i (t<64) or f (t>=64)
    const int j1 = t + 128;    // gate row B: g (t<64) or o (t>=64)

    // ---- W_hh rows into registers as k-pairs (64 x u64 = 128 regs) ----
    u64 wA[HID / 2], wB[HID / 2];
    {
        const u64* w64 = reinterpret_cast<const u64*>(w_hh);
        const u64* pa = w64 + (size_t)j0 * (HID / 2);
        const u64* pb = w64 + (size_t)j1 * (HID / 2);
#pragma unroll
        for (int k = 0; k < HID / 2; ++k) { wA[k] = pa[k]; wB[k] = pb[k]; }
    }

    const float wihA  = w_ih[j0];
    const float wihB  = w_ih[j1];
    const float biasA = b_ih[j0] + b_hh[j0];
    const float biasB = b_ih[j1] + b_hh[j1];

    // ---- stage x: rows b0..b0+3 are contiguous in global (I=1) ----
    {
        const float4* src = reinterpret_cast<const float4*>(x + (size_t)b0 * TSTEPS);
        float4* dst = reinterpret_cast<float4*>(sh_x);
#pragma unroll
        for (int i = 0; i < (RPB * TSTEPS / 4) / NTHR; ++i)   // 4 iters
            dst[t + i * NTHR] = src[t + i * NTHR];
    }
    // init h = 0
#pragma unroll
    for (int i = t; i < RPB * HID; i += NTHR)
        (&sh_h[0][0])[i] = 0.0f;

    // phase-2 ownership: update u0=t and u1=t+128 of the RPB*64 (row, m) cells
    const int r0 = t >> 6,          m0 = t & 63;
    const int r1 = (t + 128) >> 6,  m1 = t & 63;
    float c0 = 0.0f, c1 = 0.0f;

    __syncthreads();

    for (int step = 0; step < TSTEPS; ++step) {
        // ---------- phase 1: gate pre-activations (f32x2 dot over k) ----------
        u64 aA[RPB], aB[RPB];
#pragma unroll
        for (int r = 0; r < RPB; ++r) { aA[r] = 0ull; aB[r] = 0ull; }

#pragma unroll
        for (int kk = 0; kk < HID / 4; ++kk) {       // 16 iters, LDS.128 each row
#pragma unroll
            for (int r = 0; r < RPB; ++r) {
                ulonglong2 hv = *(reinterpret_cast<const ulonglong2*>(&sh_h[r][0]) + kk);
                fma2(aA[r], hv.x, wA[2 * kk]);
                fma2(aA[r], hv.y, wA[2 * kk + 1]);
                fma2(aB[r], hv.x, wB[2 * kk]);
                fma2(aB[r], hv.y, wB[2 * kk + 1]);
            }
        }

        float gA[RPB], gB[RPB];
#pragma unroll
        for (int r = 0; r < RPB; ++r) {
            float xv = sh_x[r * TSTEPS + step];
            float2 pa = unpack2(aA[r]);
            float2 pb = unpack2(aB[r]);
            gA[r] = (pa.x + pa.y) + fmaf(xv, wihA, biasA);
            gB[r] = (pb.x + pb.y) + fmaf(xv, wihB, biasB);
        }

        if (t < 64) {   // warp-uniform: warps 0,1 -> (i, g)
#pragma unroll
            for (int r = 0; r < RPB; ++r) {
                sh_g[r][j0] = fast_sigmoid(gA[r]);   // i
                sh_g[r][j1] = fast_tanh(gB[r]);      // g
            }
        } else {        // warps 2,3 -> (f, o)
#pragma unroll
            for (int r = 0; r < RPB; ++r) {
                sh_g[r][j0] = fast_sigmoid(gA[r]);   // f
                sh_g[r][j1] = fast_sigmoid(gB[r]);   // o
            }
        }
        __syncthreads();

        // ---------- phase 2: c/h update (2 cells per thread) ----------
        {
            float iv = sh_g[r0][m0];
            float fv = sh_g[r0][64 + m0];
            float gv = sh_g[r0][128 + m0];
            float ov = sh_g[r0][192 + m0];
            c0 = fmaf(fv, c0, iv * gv);
            sh_h[r0][m0] = ov * fast_tanh(c0);
        }
        {
            float iv = sh_g[r1][m1];
            float fv = sh_g[r1][64 + m1];
            float gv = sh_g[r1][128 + m1];
            float ov = sh_g[r1][192 + m1];
            c1 = fmaf(fv, c1, iv * gv);
            sh_h[r1][m1] = ov * fast_tanh(c1);
        }
        __syncthreads();
    }

    // ---------- output projection: out[b] = h_last . w_lin + b_lin ----------
    if (t < RPB) {
        float s = b_lin[0];
#pragma unroll
        for (int k = 0; k < HID; ++k)
            s = fmaf(sh_h[t][k], w_lin[k], s);
        out[b0 + t] = s;
    }
}

extern "C" void kernel_launch(void* const* d_in, const int* in_sizes, int n_in,
                              void* d_out, int out_size) {
    const float* x     = (const float*)d_in[0];
    const float* w_ih  = (const float*)d_in[1];
    const float* w_hh  = (const float*)d_in[2];
    const float* b_ih  = (const float*)d_in[3];
    const float* b_hh  = (const float*)d_in[4];
    const float* w_lin = (const float*)d_in[5];
    const float* b_lin = (const float*)d_in[6];
    float* out = (float*)d_out;

    lstm_fused_kernel<<<BATCH / RPB, NTHR>>>(x, w_ih, w_hh, b_ih, b_hh,
                                             w_lin, b_lin, out);
}

// round 7
// speedup vs baseline: 1.1636x; 1.1636x over previous
#include <cuda_runtime.h>

// LSTM: B=2048, T=512, I=1, H=64, gates=256 (i,f,g,o), O=1. fp32 throughout.
// Grid: 296 CTAs x 128 threads = exactly 2 CTAs per SM on 148 SMs (one
// perfectly balanced wave). Each CTA owns RPB=7 batch rows for the whole
// T=512 recurrence. Thread t owns gate rows t and t+128 of W_hh in registers
// (f32x2-packed over k) and computes those two gate pre-activations for all
// 7 rows per step via fma.rn.f32x2 (14 independent accumulator chains).
// __launch_bounds__(128,2) gives a 256-reg budget -> ~75 spare regs for
// LDS software pipelining. h in SMEM (broadcast LDS.128), c in registers of
// the phase-2 owner. Two __syncthreads per step.

#define BATCH  2048
#define TSTEPS 512
#define HID    64
#define G4     256
#define RPB    7
#define NTHR   128
#define GRID   296   // 2 x 148 SMs, exact single wave (296*7 = 2072 >= 2048)

typedef unsigned long long u64;

__device__ __forceinline__ void fma2(u64 &acc, u64 a, u64 b) {
    asm("fma.rn.f32x2 %0, %1, %2, %0;" : "+l"(acc) : "l"(a), "l"(b));
}

__device__ __forceinline__ float2 unpack2(u64 v) {
    float2 r;
    asm("mov.b64 {%0, %1}, %2;" : "=f"(r.x), "=f"(r.y) : "l"(v));
    return r;
}

// sigmoid(x) = 1 / (1 + 2^(-x*log2e)).  ex2.approx/rcp.approx err ~2^-22.
__device__ __forceinline__ float fast_sigmoid(float x) {
    float e, r;
    asm("ex2.approx.f32 %0, %1;" : "=f"(e) : "f"(x * -1.4426950408889634f));
    asm("rcp.approx.f32 %0, %1;" : "=f"(r) : "f"(1.0f + e));
    return r;
}

// tanh(x) = 1 - 2 / (1 + 2^(x*2*log2e)).  Saturates correctly at +-inf.
__device__ __forceinline__ float fast_tanh(float x) {
    float e, r;
    asm("ex2.approx.f32 %0, %1;" : "=f"(e) : "f"(x * 2.8853900817779268f));
    asm("rcp.approx.f32 %0, %1;" : "=f"(r) : "f"(1.0f + e));
    return fmaf(-2.0f, r, 1.0f);
}

__global__ __launch_bounds__(NTHR, 2)
void lstm_fused_kernel(const float* __restrict__ x,      // [B, T, 1]
                       const float* __restrict__ w_ih,   // [256, 1]
                       const float* __restrict__ w_hh,   // [256, 64]
                       const float* __restrict__ b_ih,   // [256]
                       const float* __restrict__ b_hh,   // [256]
                       const float* __restrict__ w_lin,  // [1, 64]
                       const float* __restrict__ b_lin,  // [1]
                       float* __restrict__ out)          // [B, 1]
{
    __shared__ float sh_x[RPB * TSTEPS];   // 14 KB: x for the 7 rows
    __shared__ float sh_h[RPB][HID];       // 1.75 KB: current h
    __shared__ float sh_g[RPB][G4];        // 7 KB: activated gates this step

    const int t  = threadIdx.x;
    const int b0 = blockIdx.x * RPB;
    const int j0 = t;          // gate row A: i (t<64) or f (t>=64)
    const int j1 = t + 128;    // gate row B: g (t<64) or o (t>=64)

    // ---- W_hh rows into registers as k-pairs (64 x u64 = 128 regs) ----
    u64 wA[HID / 2], wB[HID / 2];
    {
        const u64* w64 = reinterpret_cast<const u64*>(w_hh);
        const u64* pa = w64 + (size_t)j0 * (HID / 2);
        const u64* pb = w64 + (size_t)j1 * (HID / 2);
#pragma unroll
        for (int k = 0; k < HID / 2; ++k) { wA[k] = pa[k]; wB[k] = pb[k]; }
    }

    const float wihA  = w_ih[j0];
    const float wihB  = w_ih[j1];
    const float biasA = b_ih[j0] + b_hh[j0];
    const float biasB = b_ih[j1] + b_hh[j1];

    // ---- stage x: 7 rows x 512 steps = 896 float4, clamp row for tail CTA ----
    {
        const float4* src = reinterpret_cast<const float4*>(x);
        float4* dst = reinterpret_cast<float4*>(sh_x);
#pragma unroll
        for (int i = 0; i < (RPB * TSTEPS / 4) / NTHR; ++i) {   // 7 iters
            int idx = t + i * NTHR;           // [0, 896)
            int rl  = idx >> 7;               // 128 float4 per row
            int g   = b0 + rl;
            if (g > BATCH - 1) g = BATCH - 1; // clamp (garbage rows unused)
            dst[idx] = src[(size_t)g * (TSTEPS / 4) + (idx & 127)];
        }
    }
    // init h = 0
#pragma unroll
    for (int i = t; i < RPB * HID; i += NTHR)
        (&sh_h[0][0])[i] = 0.0f;

    // phase-2 ownership: thread t<64 owns (rows 0,2,4,6, cell t) -> 4 cells;
    // thread t>=64 owns (rows 1,3,5, cell t-64) -> 3 cells.
    const int m2    = t & 63;
    const int rodd  = (t >= 64) ? 1 : 0;
    const int ncell = rodd ? 3 : 4;
    float c[4] = {0.0f, 0.0f, 0.0f, 0.0f};

    __syncthreads();

    for (int step = 0; step < TSTEPS; ++step) {
        // ---------- phase 1: gate pre-activations (f32x2 dot over k) ----------
        u64 aA[RPB], aB[RPB];
#pragma unroll
        for (int r = 0; r < RPB; ++r) { aA[r] = 0ull; aB[r] = 0ull; }

#pragma unroll
        for (int kk = 0; kk < HID / 4; ++kk) {       // 16 iters
            ulonglong2 hv[RPB];
#pragma unroll
            for (int r = 0; r < RPB; ++r)
                hv[r] = *(reinterpret_cast<const ulonglong2*>(&sh_h[r][0]) + kk);
#pragma unroll
            for (int r = 0; r < RPB; ++r) {
                fma2(aA[r], hv[r].x, wA[2 * kk]);
                fma2(aA[r], hv[r].y, wA[2 * kk + 1]);
                fma2(aB[r], hv[r].x, wB[2 * kk]);
                fma2(aB[r], hv[r].y, wB[2 * kk + 1]);
            }
        }

#pragma unroll
        for (int r = 0; r < RPB; ++r) {
            float xv = sh_x[r * TSTEPS + step];
            float2 pa = unpack2(aA[r]);
            float2 pb = unpack2(aB[r]);
            float gA = (pa.x + pa.y) + fmaf(xv, wihA, biasA);
            float gB = (pb.x + pb.y) + fmaf(xv, wihB, biasB);
            if (t < 64) {                       // warp-uniform: warps 0,1 -> (i, g)
                sh_g[r][j0] = fast_sigmoid(gA);
                sh_g[r][j1] = fast_tanh(gB);
            } else {                            // warps 2,3 -> (f, o)
                sh_g[r][j0] = fast_sigmoid(gA);
                sh_g[r][j1] = fast_sigmoid(gB);
            }
        }
        __syncthreads();

        // ---------- phase 2: c/h update (3-4 cells per thread) ----------
#pragma unroll
        for (int q = 0; q < 4; ++q) {
            if (q < ncell) {
                int r = 2 * q + rodd;
                float iv = sh_g[r][m2];
                float fv = sh_g[r][64 + m2];
                float gv = sh_g[r][128 + m2];
                float ov = sh_g[r][192 + m2];
                c[q] = fmaf(fv, c[q], iv * gv);
                sh_h[r][m2] = ov * fast_tanh(c[q]);
            }
        }
        __syncthreads();
    }

    // ---------- output projection: out[b] = h_last . w_lin + b_lin ----------
    if (t < RPB && (b0 + t) < BATCH) {
        float s = b_lin[0];
#pragma unroll
        for (int k = 0; k < HID; ++k)
            s = fmaf(sh_h[t][k], w_lin[k], s);
        out[b0 + t] = s;
    }
}

extern "C" void kernel_launch(void* const* d_in, const int* in_sizes, int n_in,
                              void* d_out, int out_size) {
    const float* x     = (const float*)d_in[0];
    const float* w_ih  = (const float*)d_in[1];
    const float* w_hh  = (const float*)d_in[2];
    const float* b_ih  = (const float*)d_in[3];
    const float* b_hh  = (const float*)d_in[4];
    const float* w_lin = (const float*)d_in[5];
    const float* b_lin = (const float*)d_in[6];
    float* out = (float*)d_out;

    lstm_fused_kernel<<<GRID, NTHR>>>(x, w_ih, w_hh, b_ih, b_hh,
                                      w_lin, b_lin, out);
}

// round 8
// speedup vs baseline: 1.4530x; 1.2488x over previous
#include <cuda_runtime.h>

// LSTM: B=2048, T=512, I=1, H=64, gates=256 (i,f,g,o), O=1. fp32 throughout.
// Grid: 296 CTAs x 128 threads = exactly 2 CTAs per SM (one balanced wave).
// Each CTA owns RPB=7 batch rows for the full T=512 recurrence.
//
// Cell-aligned gate ownership: warp w covers cells m in [16w, 16w+16).
//   lane l<16  owns gate rows m       (i) and m+128 (g) of cell m=16w+l
//   lane l>=16 owns gate rows m+64    (f) and m+192 (o) of cell m=16w+(l-16)
// After activation, (f,o) reach the (i,g) lane via two shfl.xor(16) — no SMEM
// gate exchange, no second barrier. h is double-buffered in SMEM so each step
// needs exactly ONE __syncthreads. W_hh rows live in registers (f32x2-packed),
// dots via fma.rn.f32x2 with 14 independent accumulator chains.

#define BATCH  2048
#define TSTEPS 512
#define HID    64
#define RPB    7
#define NTHR   128
#define GRID   296   // 2 x 148 SMs; 296*7 = 2072 >= 2048 (tail clamped)

typedef unsigned long long u64;

__device__ __forceinline__ void fma2(u64 &acc, u64 a, u64 b) {
    asm("fma.rn.f32x2 %0, %1, %2, %0;" : "+l"(acc) : "l"(a), "l"(b));
}

__device__ __forceinline__ float2 unpack2(u64 v) {
    float2 r;
    asm("mov.b64 {%0, %1}, %2;" : "=f"(r.x), "=f"(r.y) : "l"(v));
    return r;
}

__device__ __forceinline__ float ex2f(float x) {
    float e;
    asm("ex2.approx.f32 %0, %1;" : "=f"(e) : "f"(x));
    return e;
}
__device__ __forceinline__ float rcpf(float x) {
    float r;
    asm("rcp.approx.f32 %0, %1;" : "=f"(r) : "f"(x));
    return r;
}

// tanh(x) = 1 - 2/(1 + 2^(2x*log2e)); saturates correctly at +-inf.
__device__ __forceinline__ float fast_tanh(float x) {
    return fmaf(-2.0f, rcpf(1.0f + ex2f(x * 2.8853900817779268f)), 1.0f);
}

__global__ __launch_bounds__(NTHR, 2)
void lstm_fused_kernel(const float* __restrict__ x,      // [B, T, 1]
                       const float* __restrict__ w_ih,   // [256, 1]
                       const float* __restrict__ w_hh,   // [256, 64]
                       const float* __restrict__ b_ih,   // [256]
                       const float* __restrict__ b_hh,   // [256]
                       const float* __restrict__ w_lin,  // [1, 64]
                       const float* __restrict__ b_lin,  // [1]
                       float* __restrict__ out)          // [B, 1]
{
    __shared__ float sh_x[RPB * TSTEPS];      // 14 KB
    __shared__ float sh_h[2][RPB][HID];       // 3.5 KB, double-buffered

    const int t  = threadIdx.x;
    const int l  = t & 31;
    const int w  = t >> 5;
    const int b0 = blockIdx.x * RPB;

    const int  m  = (w << 4) + (l & 15);      // cell this thread serves
    const bool hi = (l & 16) != 0;            // upper half-warp = (f,o) owner
    const int  jA = m + (hi ? 64 : 0);        // i-row (lo) / f-row (hi)
    const int  jB = jA + 128;                 // g-row (lo) / o-row (hi)

    // ---- W_hh rows into registers as k-pairs (64 x u64 = 128 regs) ----
    u64 wA[HID / 2], wB[HID / 2];
    {
        const u64* w64 = reinterpret_cast<const u64*>(w_hh);
        const u64* pa = w64 + (size_t)jA * (HID / 2);
        const u64* pb = w64 + (size_t)jB * (HID / 2);
#pragma unroll
        for (int k = 0; k < HID / 2; ++k) { wA[k] = pa[k]; wB[k] = pb[k]; }
    }

    const float wihA  = w_ih[jA];
    const float wihB  = w_ih[jB];
    const float biasA = b_ih[jA] + b_hh[jA];
    const float biasB = b_ih[jB] + b_hh[jB];

    // Branchless activation constants for gate B:
    //   lo (g-gate, tanh):    act = -2*rcp(1+ex2( 2*log2e * x)) + 1
    //   hi (o-gate, sigmoid): act =  1*rcp(1+ex2(  -log2e * x)) + 0
    const float L2E = 1.4426950408889634f;
    const float Bc = hi ? -L2E : 2.0f * L2E;
    const float Ac = hi ? 1.0f : -2.0f;
    const float Cc = hi ? 0.0f : 1.0f;

    // ---- stage x: 7 rows x 512 steps = 896 float4, clamp row for tail CTA ----
    {
        const float4* src = reinterpret_cast<const float4*>(x);
        float4* dst = reinterpret_cast<float4*>(sh_x);
#pragma unroll
        for (int i = 0; i < (RPB * TSTEPS / 4) / NTHR; ++i) {   // 7 iters
            int idx = t + i * NTHR;            // [0, 896)
            int rl  = idx >> 7;                // 128 float4 per row
            int g   = b0 + rl;
            if (g > BATCH - 1) g = BATCH - 1;  // clamp (garbage rows unused)
            dst[idx] = src[(size_t)g * (TSTEPS / 4) + (idx & 127)];
        }
    }
    // init h buffer 0 = 0
#pragma unroll
    for (int i = t; i < RPB * HID; i += NTHR)
        (&sh_h[0][0][0])[i] = 0.0f;

    float c[RPB];
#pragma unroll
    for (int r = 0; r < RPB; ++r) c[r] = 0.0f;

    __syncthreads();

    for (int step = 0; step < TSTEPS; ++step) {
        const int rb = step & 1;               // read buffer
        const int wb = rb ^ 1;                 // write buffer

        // ---------- gate pre-activations: f32x2 dot over k, 14 chains ----------
        u64 aA[RPB], aB[RPB];
#pragma unroll
        for (int r = 0; r < RPB; ++r) { aA[r] = 0ull; aB[r] = 0ull; }

#pragma unroll
        for (int kk = 0; kk < HID / 4; ++kk) {  // 16 iters, LDS.128 broadcast
            ulonglong2 hv[RPB];
#pragma unroll
            for (int r = 0; r < RPB; ++r)
                hv[r] = *(reinterpret_cast<const ulonglong2*>(&sh_h[rb][r][0]) + kk);
#pragma unroll
            for (int r = 0; r < RPB; ++r) {
                fma2(aA[r], hv[r].x, wA[2 * kk]);
                fma2(aA[r], hv[r].y, wA[2 * kk + 1]);
                fma2(aB[r], hv[r].x, wB[2 * kk]);
                fma2(aB[r], hv[r].y, wB[2 * kk + 1]);
            }
        }

        // ---------- activations (branchless, warp stays convergent) ----------
        float actA[RPB], actB[RPB];
#pragma unroll
        for (int r = 0; r < RPB; ++r) {
            float xv = sh_x[r * TSTEPS + step];
            float2 pa = unpack2(aA[r]);
            float2 pb = unpack2(aB[r]);
            float gAv = (pa.x + pa.y) + fmaf(xv, wihA, biasA);
            float gBv = (pb.x + pb.y) + fmaf(xv, wihB, biasB);
            // gate A is always a sigmoid (i for lo lanes, f for hi lanes)
            actA[r] = rcpf(1.0f + ex2f(gAv * -L2E));
            // gate B: tanh (lo) / sigmoid (hi) via per-lane constants
            actB[r] = fmaf(Ac, rcpf(1.0f + ex2f(gBv * Bc)), Cc);
        }

        // ---------- exchange (f,o) via shfl, update c/h, store h ----------
#pragma unroll
        for (int r = 0; r < RPB; ++r) {
            float fv = __shfl_xor_sync(0xFFFFFFFFu, actA[r], 16);  // f for lo lanes
            float ov = __shfl_xor_sync(0xFFFFFFFFu, actB[r], 16);  // o for lo lanes
            c[r] = fmaf(fv, c[r], actA[r] * actB[r]);  // f*c + i*g (lo lanes)
            float hval = ov * fast_tanh(c[r]);
            if (!hi) sh_h[wb][r][m] = hval;            // one owner per (r, m)
        }
        __syncthreads();
    }

    // ---------- output projection: out[b] = h_last . w_lin + b_lin ----------
    // Last write went to buffer wb = (511 & 1) ^ 1 = 0.
    if (t < RPB && (b0 + t) < BATCH) {
        float s = b_lin[0];
#pragma unroll
        for (int k = 0; k < HID; ++k)
            s = fmaf(sh_h[0][t][k], w_lin[k], s);
        out[b0 + t] = s;
    }
}

extern "C" void kernel_launch(void* const* d_in, const int* in_sizes, int n_in,
                              void* d_out, int out_size) {
    const float* x     = (const float*)d_in[0];
    const float* w_ih  = (const float*)d_in[1];
    const float* w_hh  = (const float*)d_in[2];
    const float* b_ih  = (const float*)d_in[3];
    const float* b_hh  = (const float*)d_in[4];
    const float* w_lin = (const float*)d_in[5];
    const float* b_lin = (const float*)d_in[6];
    float* out = (float*)d_out;

    lstm_fused_kernel<<<GRID, NTHR>>>(x, w_ih, w_hh, b_ih, b_hh,
                                      w_lin, b_lin, out);
}